// round 17
// baseline (speedup 1.0000x reference)
#include <cuda_runtime.h>
#include <cuda_fp16.h>

#define B_ 128
#define T_ 4096
#define I_ 64
#define H_ 128
#define G_ 384   /* 3*H */
#define C_ 2
#define ALPHA_ 0.3f
#define BETA_  0.5f

#define CH_   256   /* EMA chunk length  */
#define HALO_ 64    /* EMA warm-up halo: trunc err ~0.5^64 */

// Scratch (device globals: allocation-free per harness rules)
__device__ float  g_x2[(long)B_ * T_ * I_];            // 134 MB
__device__ __half g_xp[(long)B_ * T_ * G_ + 3 * G_];   // 403 MB (+3-row pad)
__device__ float  g_st11[B_ * C_];
__device__ float  g_st12[B_ * C_];

// ---------------- packed f32x2 helpers (sm_100+) ----------------
__device__ __forceinline__ unsigned long long pack2_(float lo, float hi) {
    unsigned long long r;
    asm("mov.b64 %0, {%1, %2};" : "=l"(r) : "f"(lo), "f"(hi));
    return r;
}
__device__ __forceinline__ float2 unpack2_(unsigned long long v) {
    float2 r;
    asm("mov.b64 {%0, %1}, %2;" : "=f"(r.x), "=f"(r.y) : "l"(v));
    return r;
}
__device__ __forceinline__ void fma2_(unsigned long long& d,
                                      unsigned long long a,
                                      unsigned long long b) {
    asm("fma.rn.f32x2 %0, %1, %2, %0;" : "+l"(d) : "l"(a), "l"(b));
}
__device__ __forceinline__ float tanh_hw_(float x) {
    float r;
    asm("tanh.approx.f32 %0, %1;" : "=f"(r) : "f"(x));
    return r;
}
__device__ __forceinline__ float sigm_hw_(float x) {
    return fmaf(tanh_hw_(0.5f * x), 0.5f, 0.5f);
}
__device__ __forceinline__ unsigned int to_tf32_(float v) {
    unsigned int u;
    asm("cvt.rna.tf32.f32 %0, %1;" : "=r"(u) : "f"(v));
    return u;
}

// ---------------------------------------------------------------------------
// Kernel 1: chained EMAs, chunked-parallel with decay halo.  (unchanged)
// ---------------------------------------------------------------------------
__global__ __launch_bounds__(64) void ema_kernel(const float* __restrict__ x) {
    int nchunk = T_ / CH_;
    int c = blockIdx.x % nchunk;
    int b = blockIdx.x / nchunk;
    int i = threadIdx.x;

    const float* xin = x + (long)b * T_ * I_ + i;
    float* o = g_x2 + (long)b * T_ * I_ + i;

    int t0 = c * CH_;
    int ts = (c == 0) ? 0 : (t0 - HALO_);

    float x1 = xin[(long)ts * I_];
    float x2 = x1;

#pragma unroll 4
    for (int t = ts + 1; t < t0; ++t) {
        float xt = xin[(long)t * I_];
        x1 = fmaf(ALPHA_, x1, (1.f - ALPHA_) * xt);
        x2 = fmaf(BETA_, x2, (1.f - BETA_) * x1);
    }

    if (c == 0) o[0] = x2;
    int tb = (c == 0) ? 1 : t0;
#pragma unroll 4
    for (int t = tb; t < t0 + CH_; ++t) {
        float xt = xin[(long)t * I_];
        x1 = fmaf(ALPHA_, x1, (1.f - ALPHA_) * xt);
        x2 = fmaf(BETA_, x2, (1.f - BETA_) * x1);
        o[(long)t * I_] = x2;
    }

    if (c == nchunk - 1 && (i == 1 || i == 2)) {
        g_st11[b * C_ + (i - 1)] = x1;
        g_st12[b * C_ + (i - 1)] = x2;
    }
}

// ---------------------------------------------------------------------------
// Kernel 2: xp = x2 @ W_ih^T + b_ih via tf32 mma.sync.m16n8k8, fp16 output.
// CTA: 384 threads (12 warps), M=64 rows, N=384, K=64. Warp w owns n-slice
// [32w, 32w+32): B in registers, A tile in smem (padded, conflict-free).
// ---------------------------------------------------------------------------
#define XS_STRIDE 68
__global__ __launch_bounds__(384) void xp_mma_kernel(
    const float* __restrict__ W_ih, const float* __restrict__ b_ih) {
    __shared__ unsigned int xs[64 * XS_STRIDE];   // 17408 B

    int tid = threadIdx.x;
    int m0 = blockIdx.x * 64;

    // fill A tile (coalesced gmem read, cvt to tf32)
    for (int idx = tid; idx < 64 * I_; idx += 384) {
        xs[(idx >> 6) * XS_STRIDE + (idx & 63)] = to_tf32_(g_x2[(long)m0 * I_ + idx]);
    }

    int w = tid >> 5;
    int lane = tid & 31;
    int lr = lane >> 2;           // 0..7
    int lc = lane & 3;            // 0..3
    int ng = 32 * w;              // warp's n-slice base

    // B fragments in registers: breg[kc][nt][r] = W_ih[(ng+8nt+lr)][8kc+lc+4r]
    unsigned int breg[8][4][2];
#pragma unroll
    for (int nt = 0; nt < 4; ++nt) {
        const float* wrow = W_ih + (ng + 8 * nt + lr) * I_ + lc;
#pragma unroll
        for (int kc = 0; kc < 8; ++kc) {
            breg[kc][nt][0] = to_tf32_(wrow[8 * kc]);
            breg[kc][nt][1] = to_tf32_(wrow[8 * kc + 4]);
        }
    }
    // bias per nt (cols ng + 8nt + 2lc, +1)
    float bl[4], bh[4];
#pragma unroll
    for (int nt = 0; nt < 4; ++nt) {
        bl[nt] = b_ih[ng + 8 * nt + 2 * lc];
        bh[nt] = b_ih[ng + 8 * nt + 2 * lc + 1];
    }
    __syncthreads();

#pragma unroll
    for (int mt = 0; mt < 4; ++mt) {
        int mb = 16 * mt;
        float c[4][4];
#pragma unroll
        for (int nt = 0; nt < 4; ++nt) {
            c[nt][0] = bl[nt]; c[nt][1] = bh[nt];   // row lr
            c[nt][2] = bl[nt]; c[nt][3] = bh[nt];   // row lr+8
        }
#pragma unroll
        for (int kc = 0; kc < 8; ++kc) {
            int k0 = 8 * kc;
            unsigned int a0 = xs[(mb + lr) * XS_STRIDE + k0 + lc];
            unsigned int a1 = xs[(mb + lr + 8) * XS_STRIDE + k0 + lc];
            unsigned int a2 = xs[(mb + lr) * XS_STRIDE + k0 + lc + 4];
            unsigned int a3 = xs[(mb + lr + 8) * XS_STRIDE + k0 + lc + 4];
#pragma unroll
            for (int nt = 0; nt < 4; ++nt) {
                asm volatile(
                    "mma.sync.aligned.m16n8k8.row.col.f32.tf32.tf32.f32 "
                    "{%0,%1,%2,%3}, {%4,%5,%6,%7}, {%8,%9}, {%0,%1,%2,%3};"
                    : "+f"(c[nt][0]), "+f"(c[nt][1]),
                      "+f"(c[nt][2]), "+f"(c[nt][3])
                    : "r"(a0), "r"(a1), "r"(a2), "r"(a3),
                      "r"(breg[kc][nt][0]), "r"(breg[kc][nt][1]));
            }
        }
        // store fp16: rows m0+mb+lr (c0,c1), m0+mb+lr+8 (c2,c3)
        long r0 = (long)(m0 + mb + lr) * G_;
        long r1 = r0 + 8 * G_;
#pragma unroll
        for (int nt = 0; nt < 4; ++nt) {
            int col = ng + 8 * nt + 2 * lc;       // even -> 4B aligned
            *(__half2*)(g_xp + r0 + col) = __floats2half2_rn(c[nt][0], c[nt][1]);
            *(__half2*)(g_xp + r1 + col) = __floats2half2_rn(c[nt][2], c[nt][3]);
        }
    }
}

// ---------------------------------------------------------------------------
// Kernel 3: GRU scan — ASYMMETRIC gate split, 256 threads, one batch/CTA,
// double-buffered h (race-free single barrier).
// Thread (j = tid/2, p = tid&1):
//   p0: FULL W_r row j (64 f32x2) + W_n row j cols [0,64)  (32 f32x2)
//   p1: FULL W_z row j (64 f32x2) + W_n row j cols [64,128)(32 f32x2)
// => Ar, Az complete with NO shfl; r,z computed in parallel on partner
// lanes; only 2 shfls (Gn partial, z hand-off). Plain h layout (broadcast).
// ---------------------------------------------------------------------------
__global__ __launch_bounds__(256, 1) void gru_kernel(
    const float* __restrict__ W_hh, const float* __restrict__ b_hh,
    const float* __restrict__ W_fc, const float* __restrict__ b_fc,
    float* __restrict__ out) {
    __shared__ __align__(16) float shw0[H_], shw1[H_];  // h ping/pong

    int tid = threadIdx.x;
    int j = tid >> 1;
    int p = tid & 1;
    int b = blockIdx.x;
    int noff = 16 * p;              // n-pass chunk base (16B chunks)

    // main row (r for p0, z for p1): 64 f32x2; n half: 32 f32x2
    unsigned long long wm[64], wn[32];
    {
        const unsigned long long* rm =
            (const unsigned long long*)(W_hh + (p ? H_ + j : j) * H_);
#pragma unroll
        for (int k = 0; k < 64; ++k) wm[k] = rm[k];
        const unsigned long long* rn =
            (const unsigned long long*)(W_hh + (2 * H_ + j) * H_ + 64 * p);
#pragma unroll
        for (int k = 0; k < 32; ++k) wn[k] = rn[k];
    }
    float bm = p ? b_hh[H_ + j] : b_hh[j];     // main-gate bias
    float bn = p ? b_hh[2 * H_ + j] : 0.f;     // b_n folded on p1

    // gi streams (fp16, prefetch depth 2):
    //   gpA: p0 -> i_r (col j),    p1 -> i_z (col H+j)
    //   gpN: p0 -> i_n (col 2H+j), p1 -> dup i_z (unused)
    const __half* gpA = g_xp + (long)b * T_ * G_ + (p ? H_ + j : j);
    const __half* gpN = gpA + (p ? 0 : 2 * H_);
    float a0 = __half2float(gpA[0]), a1 = __half2float(gpA[G_]);
    float n0 = __half2float(gpN[0]), n1 = __half2float(gpN[G_]);
    gpA += 2 * G_;
    gpN += 2 * G_;

    if (tid < H_) { shw0[tid] = 0.f; shw1[tid] = 0.f; }
    float hprev = 0.f;
    __syncthreads();

// One GRU step: read h(t-1) from RBUF, write h(t) to WBUF (race-free).
#define GRU_STEP(RBUF, WBUF)                                                 \
    do {                                                                     \
        float a2 = __half2float(gpA[0]);                                     \
        float n2 = __half2float(gpN[0]);                                     \
        gpA += G_; gpN += G_;                                                \
        const ulonglong2* hs = (const ulonglong2*)(RBUF);                    \
        unsigned long long am = pack2_(bm + a0, 0.f);                        \
        _Pragma("unroll")                                                    \
        for (int k = 0; k < 32; ++k) {     /* full main row: broadcast */    \
            ulonglong2 hv = hs[k];                                           \
            fma2_(am, wm[2 * k + 0], hv.x);                                  \
            fma2_(am, wm[2 * k + 1], hv.y);                                  \
        }                                                                    \
        float2 fm = unpack2_(am);                                            \
        float gv = sigm_hw_(fm.x + fm.y);  /* r on p0, z on p1 (parallel) */ \
        unsigned long long an = pack2_(bn, 0.f);                             \
        _Pragma("unroll")                                                    \
        for (int k = 0; k < 16; ++k) {     /* n half-row */                  \
            ulonglong2 hv = hs[noff + k];                                    \
            fma2_(an, wn[2 * k + 0], hv.x);                                  \
            fma2_(an, wn[2 * k + 1], hv.y);                                  \
        }                                                                    \
        float2 fn = unpack2_(an);                                            \
        float Gnp = fn.x + fn.y;                                             \
        float Gn = Gnp + __shfl_xor_sync(0xffffffffu, Gnp, 1);               \
        float zsh = __shfl_xor_sync(0xffffffffu, gv, 1);  /* p0 <- z */      \
        if (p == 0) {                                                        \
            float n = tanh_hw_(fmaf(gv, Gn, n0));   /* gv = r here */        \
            hprev = fmaf(zsh, hprev - n, n);                                 \
            (WBUF)[j] = hprev;                                               \
        }                                                                    \
        __syncthreads();                                                     \
        a0 = a1; a1 = a2;  n0 = n1; n1 = n2;                                 \
    } while (0)

    for (int t = 0; t < T_; t += 2) {
        GRU_STEP(shw0, shw1);      // even t: read 0, write 1
        GRU_STEP(shw1, shw0);      // odd  t: read 1, write 0
    }
#undef GRU_STEP
    // T_ even: final h lives in shw0 (plain layout).

    if (tid < C_) {
        float o = b_fc[tid];
        const float* wf = W_fc + tid * H_;
#pragma unroll 8
        for (int jj = 0; jj < H_; ++jj)
            o = fmaf(shw0[jj], wf[jj], o);
        o = (o - BETA_ * g_st12[b * C_ + tid]) / (1.f - BETA_);
        o = (o - ALPHA_ * g_st11[b * C_ + tid]) / (1.f - ALPHA_);
        out[b * C_ + tid] = o;
    }
}

// ---------------------------------------------------------------------------
extern "C" void kernel_launch(void* const* d_in, const int* in_sizes, int n_in,
                              void* d_out, int out_size) {
    const float* x    = (const float*)d_in[0];
    const float* W_ih = (const float*)d_in[1];
    const float* W_hh = (const float*)d_in[2];
    const float* b_ih = (const float*)d_in[3];
    const float* b_hh = (const float*)d_in[4];
    const float* W_fc = (const float*)d_in[5];
    const float* b_fc = (const float*)d_in[6];
    float* out = (float*)d_out;

    ema_kernel<<<B_ * (T_ / CH_), 64>>>(x);
    xp_mma_kernel<<<(B_ * T_) / 64, 384>>>(W_ih, b_ih);
    gru_kernel<<<B_, 256>>>(W_hh, b_hh, W_fc, b_fc, out);
}